// round 12
// baseline (speedup 1.0000x reference)
#include <cuda_runtime.h>
#include <math.h>
#include <stdint.h>

#define BB 2
#define LL 4096
#define CC 64
#define DI 128
#define SS 16
#define TT 56          // positions per tile
#define NP 58          // TT + 2 halo
#define NPX 60         // xnT row stride (16B-aligned)
#define TSTR 60        // transposed [d][pos] stride (16B-aligned: 240B)
#define NTILES 74      // ceil(4096/56)
#define NTH 512
#define GRID (BB*NTILES)   // 148 CTAs = one full wave at 1 CTA/SM

typedef unsigned long long ull;
union F4U2 { float4 f4; ull u2[2]; };

__device__ __forceinline__ ull fma2(ull a, ull b, ull c) {
    ull d; asm("fma.rn.f32x2 %0, %1, %2, %3;" : "=l"(d) : "l"(a), "l"(b), "l"(c));
    return d;
}
__device__ __forceinline__ ull mul2(ull a, ull b) {
    ull d; asm("mul.rn.f32x2 %0, %1, %2;" : "=l"(d) : "l"(a), "l"(b));
    return d;
}
__device__ __forceinline__ ull pack2(float lo, float hi) {
    ull d; asm("mov.b64 %0, {%1, %2};" : "=l"(d) : "f"(lo), "f"(hi));
    return d;
}
__device__ __forceinline__ void unpack2(ull v, float& lo, float& hi) {
    asm("mov.b64 {%0, %1}, %2;" : "=f"(lo), "=f"(hi) : "l"(v));
}

// -------- scratch (device globals; no dynamic allocation allowed) --------
__device__ float g_rgbT[BB*LL*CC];   // [b][l][c]
__device__ float g_dteT[BB*LL*CC];
__device__ float g_buf0[BB*LL*CC];
__device__ float g_buf1[BB*LL*CC];
__device__ float g_wT[64*256];             // in_proj transposed [d][row]
__device__ float g_hperm[BB*LL*DI*SS];     // permuted h chain [b][l][sg][dd][4]
__device__ float g_hfallback[BB*LL*DI*SS]; // final h if out_size unexpected
__device__ unsigned g_bar;                 // grid-sync arrival counter

__global__ void reset_kernel() { g_bar = 0u; }

__device__ __forceinline__ void grid_sync(unsigned target) {
    __syncthreads();
    if (threadIdx.x == 0) {
        __threadfence();
        atomicAdd(&g_bar, 1u);
        while (atomicAdd(&g_bar, 0u) < target) { }
        __threadfence();
    }
    __syncthreads();
}

// smem layout (floats)
#define OFF_XN      0                         // xnT [c][NPX] = 3840 (alias conv bufs)
#define OFF_XNR     (OFF_XN + 64*NPX)         // xn_r [p][64] = 3584
#define OFF_XCRAW   (OFF_XNR + TT*64)         // max(58*128, 128*60) = 7680 (alias gT, conv wT)
#define OFF_Z       (OFF_XCRAW + 7680)        // 56*128 = 7168 (alias conv_out res)
#define OFF_XCT     (OFF_Z + TT*128)          // xcT [d][TSTR] = 7680
#define OFF_XPT     (OFF_XCT + 128*TSTR)      // 8192
#define OFF_DTT     (OFF_XPT + 128*64)        // 4096
#define OFF_OPT     (OFF_DTT + 32*128)        // 8192
#define OFF_DBCBC   (OFF_OPT + 128*64)        // B/C [p][32] = 1792
#define OFF_DRAWT   (OFF_DBCBC + TT*32)       // drawT [r][TSTR] = 1920
#define OFF_CW      (OFF_DRAWT + 32*TSTR)     // 384
#define OFF_CB      (OFF_CW + 3*128)          // 128
#define OFF_DTB     (OFF_CB + 128)            // 128
#define OFF_DP      (OFF_DTB + 128)           // 128
#define OFF_NW      (OFF_DP + 128)            // 64
#define SMEM_FLOATS (OFF_NW + 64)
#define SMEM_BYTES  (SMEM_FLOATS * 4)         // ~215 KB

__global__ __launch_bounds__(NTH, 1) void fused_kernel(
    const float* __restrict__ rgb, const float* __restrict__ dte,
    const float* __restrict__ w1, const float* __restrict__ b1,
    const float* __restrict__ w2, const float* __restrict__ b2,
    const float* __restrict__ w3, const float* __restrict__ b3,
    const float* __restrict__ normw,
    const float* __restrict__ in_proj_w,
    const float* __restrict__ conv1d_w, const float* __restrict__ conv1d_b,
    const float* __restrict__ x_proj_w,
    const float* __restrict__ dt_proj_w, const float* __restrict__ dt_proj_b,
    const float* __restrict__ A_log, const float* __restrict__ Dp,
    const float* __restrict__ out_proj_w,
    float* out, float* hfinal)
{
    extern __shared__ float sm[];
    float* xn_s    = sm + OFF_XN;     // xnT [c][NPX]
    float* xn_r    = sm + OFF_XNR;    // [p][64]
    float* xcraw_s = sm + OFF_XCRAW;  // [hp][128] during 1b/ph2
    float* z_s     = sm + OFF_Z;      // [p][128]
    float* xcT     = sm + OFF_XCT;    // [d][TSTR]
    float* xprojT  = sm + OFF_XPT;    // [d][j]
    float* dtprojT = sm + OFF_DTT;    // [r][dd]
    float* outprojT= sm + OFF_OPT;    // [dd][c]
    float* dbcBC   = sm + OFF_DBCBC;  // [p][32]: B(16) | C(16)
    float* drawT   = sm + OFF_DRAWT;  // [r][TSTR]
    float* cw_s    = sm + OFF_CW;
    float* cb_s    = sm + OFF_CB;
    float* dtb_s   = sm + OFF_DTB;
    float* Dp_s    = sm + OFF_DP;
    float* nw_s    = sm + OFF_NW;
    float* gT      = xcraw_s;         // alias: [dd][TSTR] (delta_pre then g)

    const int t    = threadIdx.x;
    const int lane = t & 31;
    const int b    = blockIdx.x / NTILES;
    const int tile = blockIdx.x - b*NTILES;
    const int l0   = tile * TT;

    float* rgbT  = g_rgbT;
    float* dteT  = g_dteT;
    float* buf0  = g_buf0;
    float* buf1  = g_buf1;
    float* hperm = g_hperm;

    // fastA: is exp(A_log[dd][s]) == s+1?
    bool fastA = true;
    {
        const int dd3 = t & 127;
        #pragma unroll
        for (int s = 0; s < SS; s++) {
            float na = __expf(A_log[dd3*16 + s]);
            if (fabsf(na - (float)(s+1)) > 1e-3f) fastA = false;
        }
    }

    // ================= conv_in stage =================
    {
        float* in_s = xn_s;     // [c][TT] 3584 <= 3840
        float* wT   = xcraw_s;  // [c][65]
        for (int which = 0; which < 2; which++) {
            const float* src  = which ? dte : rgb;
            const float* w    = which ? w2 : w1;
            const float* bias = which ? b2 : b1;
            float* dst = which ? dteT : rgbT;
            __syncthreads();
            for (int lin = t; lin < 64*64; lin += NTH)
                wT[(lin & 63)*65 + (lin >> 6)] = w[lin];
            for (int lin = t; lin < 64*TT; lin += NTH) {
                int c = lin / TT, p = lin - c*TT;
                int l = l0 + p;
                in_s[c*TT + p] = (l < LL) ? src[(size_t)(b*64 + c)*LL + l] : 0.0f;
            }
            __syncthreads();
            int o = t & 63, pslot = t >> 6;
            float bv = bias[o];
            for (int p = pslot; p < TT; p += 8) {
                int l = l0 + p;
                if (l >= LL) continue;
                float acc = bv;
                #pragma unroll 8
                for (int c = 0; c < 64; c++)
                    acc += wT[c*65 + o] * in_s[c*TT + p];
                dst[(size_t)(b*LL + l)*64 + o] = acc;
            }
        }
        __syncthreads();
    }

    // CTA 0 builds the transposed in_proj copy
    if (blockIdx.x == 0) {
        for (int lin = t; lin < 64*256; lin += NTH) {
            int d = lin >> 8, r = lin & 255;
            g_wT[d*256 + r] = in_proj_w[r*64 + d];
        }
    }

    // ================= stage mamba weights (ONCE) =================
    for (int lin = t; lin < 64*128; lin += NTH) {
        int j = lin >> 7, d = lin & 127;
        xprojT[d*64 + j] = x_proj_w[lin];
    }
    for (int lin = t; lin < 128*32; lin += NTH) {
        int dd = lin >> 5, r = lin & 31;
        dtprojT[r*128 + dd] = dt_proj_w[lin];
    }
    for (int lin = t; lin < 64*128; lin += NTH) {
        int c = lin >> 7, dd = lin & 127;
        outprojT[dd*64 + c] = out_proj_w[lin];
    }
    if (t < 384) { int dd = t / 3, k = t % 3; cw_s[k*128 + dd] = conv1d_w[t]; }
    if (t < 128) { cb_s[t] = conv1d_b[t]; dtb_s[t] = dt_proj_b[t]; Dp_s[t] = Dp[t]; }
    if (t < 64)  { nw_s[t] = normw[t]; }

    unsigned ep = 1;
    grid_sync(GRID*ep); ep++;

    // ================= 6 fused residual mamba blocks =================
    for (int blk = 0; blk < 6; blk++) {
        const float* base = (blk & 1) ? dteT : rgbT;
        const float* prev = (blk == 0) ? (const float*)0
                                       : ((blk & 1) ? buf0 : buf1);
        float* outp = (blk & 1) ? buf1 : buf0;
        const int hmode = (blk == 0) ? 0 : (blk == 5 ? 2 : 1);

        // ---- phase 1a: rmsnorm -> xnT (+xn_r copy) ----
        {
            int w = t >> 5;
            for (int hp = w; hp < NP; hp += 16) {
                int l = l0 - 1 + hp;       // warp-uniform
                float o0 = 0.0f, o1 = 0.0f;
                if (l >= 0 && l < LL) {
                    size_t off = ((size_t)(b*LL + l)) * 64;
                    float v0 = base[off + lane];
                    float v1 = base[off + 32 + lane];
                    if (prev) { v0 += prev[off + lane]; v1 += prev[off + 32 + lane]; }
                    float ssum = v0*v0 + v1*v1;
                    #pragma unroll
                    for (int m = 16; m > 0; m >>= 1)
                        ssum += __shfl_xor_sync(0xffffffffu, ssum, m);
                    float rs = rsqrtf(ssum * (1.0f/64.0f) + 1e-5f);
                    o0 = v0 * rs * nw_s[lane];
                    o1 = v1 * rs * nw_s[32 + lane];
                }
                xn_s[lane*NPX + hp]        = o0;
                xn_s[(32 + lane)*NPX + hp] = o1;
                if (hp >= 1 && hp <= TT) {
                    xn_r[(hp-1)*64 + lane]      = o0;
                    xn_r[(hp-1)*64 + 32 + lane] = o1;
                }
            }
        }
        __syncthreads();

        // ---- phase 1b: in_proj GEMM (4 rows x 8 hp / thread; weights LDG) ----
        {
            const int rg  = t & 63;
            const int hpb = (t >> 6) << 3;
            ull accl[8], acch[8];
            #pragma unroll
            for (int i = 0; i < 8; i++) { accl[i] = pack2(0,0); acch[i] = pack2(0,0); }
            const float4* wp = (const float4*)g_wT;
            #pragma unroll 4
            for (int d = 0; d < 64; d++) {
                F4U2 w; w.f4 = __ldg(&wp[d*64 + rg]);
                const float4* xp = (const float4*)(xn_s + d*NPX + hpb);
                float4 xa = xp[0], xb = xp[1];
                float xs[8] = {xa.x, xa.y, xa.z, xa.w, xb.x, xb.y, xb.z, xb.w};
                #pragma unroll
                for (int i = 0; i < 8; i++) {
                    ull xd = pack2(xs[i], xs[i]);
                    accl[i] = fma2(w.u2[0], xd, accl[i]);
                    acch[i] = fma2(w.u2[1], xd, acch[i]);
                }
            }
            #pragma unroll
            for (int i = 0; i < 8; i++) {
                int hp = hpb + i;
                if (hp >= NP) break;
                F4U2 v; v.u2[0] = accl[i]; v.u2[1] = acch[i];
                if (rg < 32) {
                    *(float4*)(xcraw_s + hp*128 + rg*4) = v.f4;
                } else if (hp >= 1 && hp <= TT) {
                    *(float4*)(z_s + (hp-1)*128 + (rg-32)*4) = v.f4;
                }
            }
        }
        __syncthreads();

        // ---- phase 2: dwconv1d + silu -> xcT [d][TSTR] (transposed) ----
        for (int idx = t; idx < TT*128; idx += NTH) {
            int po = idx >> 7, dd = idx & 127;
            int hp = po + 1;
            float v = cw_s[dd]         * xcraw_s[(hp-1)*128 + dd]
                    + cw_s[128 + dd]   * xcraw_s[hp*128 + dd]
                    + cw_s[256 + dd]   * xcraw_s[(hp+1)*128 + dd]
                    + cb_s[dd];
            xcT[dd*TSTR + po] = v / (1.0f + __expf(-v));
        }
        __syncthreads();

        // ---- phase 3a: x_proj (T4P4) -> dbcBC + drawT ----
        {
            int jt = t & 15;
            int pq = t >> 4;
            if (pq < 14) {
                const int pb = pq*4;
                ull al[4], ah[4];
                #pragma unroll
                for (int i = 0; i < 4; i++) { al[i] = pack2(0,0); ah[i] = pack2(0,0); }
                #pragma unroll 4
                for (int d = 0; d < 128; d++) {
                    F4U2 w; w.f4 = *(const float4*)(xprojT + d*64 + jt*4);
                    float4 x4 = *(const float4*)(xcT + d*TSTR + pb);
                    float xs[4] = {x4.x, x4.y, x4.z, x4.w};
                    #pragma unroll
                    for (int i = 0; i < 4; i++) {
                        ull xd = pack2(xs[i], xs[i]);
                        al[i] = fma2(w.u2[0], xd, al[i]);
                        ah[i] = fma2(w.u2[1], xd, ah[i]);
                    }
                }
                if (jt >= 8) {
                    #pragma unroll
                    for (int i = 0; i < 4; i++) {
                        F4U2 o; o.u2[0] = al[i]; o.u2[1] = ah[i];
                        *(float4*)(dbcBC + (pb+i)*32 + (jt-8)*4) = o.f4;
                    }
                } else {
                    float e0[4], e1[4], e2[4], e3[4];
                    #pragma unroll
                    for (int i = 0; i < 4; i++) {
                        unpack2(al[i], e0[i], e1[i]);
                        unpack2(ah[i], e2[i], e3[i]);
                    }
                    *(float4*)(drawT + (jt*4+0)*TSTR + pb) = make_float4(e0[0],e0[1],e0[2],e0[3]);
                    *(float4*)(drawT + (jt*4+1)*TSTR + pb) = make_float4(e1[0],e1[1],e1[2],e1[3]);
                    *(float4*)(drawT + (jt*4+2)*TSTR + pb) = make_float4(e2[0],e2[1],e2[2],e2[3]);
                    *(float4*)(drawT + (jt*4+3)*TSTR + pb) = make_float4(e3[0],e3[1],e3[2],e3[3]);
                }
            }
        }
        __syncthreads();

        // ---- phase 3a2: dt_proj GEMM (K=32) -> delta_pre into gT [dd][TSTR] ----
        {
            int dq = t & 31;
            int pq = t >> 5;
            if (pq < 14) {
                const int pb = pq*4;
                float b0 = dtb_s[dq*4+0], b1 = dtb_s[dq*4+1];
                float b2v = dtb_s[dq*4+2], b3v = dtb_s[dq*4+3];
                ull al[4], ah[4];
                #pragma unroll
                for (int i = 0; i < 4; i++) { al[i] = pack2(b0,b1); ah[i] = pack2(b2v,b3v); }
                #pragma unroll 4
                for (int r = 0; r < 32; r++) {
                    F4U2 w; w.f4 = *(const float4*)(dtprojT + r*128 + dq*4);
                    float4 x4 = *(const float4*)(drawT + r*TSTR + pb);
                    float xs[4] = {x4.x, x4.y, x4.z, x4.w};
                    #pragma unroll
                    for (int i = 0; i < 4; i++) {
                        ull xd = pack2(xs[i], xs[i]);
                        al[i] = fma2(w.u2[0], xd, al[i]);
                        ah[i] = fma2(w.u2[1], xd, ah[i]);
                    }
                }
                float e0[4], e1[4], e2[4], e3[4];
                #pragma unroll
                for (int i = 0; i < 4; i++) {
                    unpack2(al[i], e0[i], e1[i]);
                    unpack2(ah[i], e2[i], e3[i]);
                }
                *(float4*)(gT + (dq*4+0)*TSTR + pb) = make_float4(e0[0],e0[1],e0[2],e0[3]);
                *(float4*)(gT + (dq*4+1)*TSTR + pb) = make_float4(e1[0],e1[1],e1[2],e1[3]);
                *(float4*)(gT + (dq*4+2)*TSTR + pb) = make_float4(e2[0],e2[1],e2[2],e2[3]);
                *(float4*)(gT + (dq*4+3)*TSTR + pb) = make_float4(e3[0],e3[1],e3[2],e3[3]);
            }
        }
        __syncthreads();

        // ---- phase 3bc: softplus(delta_pre), SSM (exp-chain), gating -> gT ----
        {
            const int dd3 = t & 127;
            const int ps4 = t >> 7;
            const float Dpv  = Dp_s[dd3];
            float4* HS = (float4*)hperm;
            float4* HD = (float4*)hfinal;
            for (int chunk = 0; chunk < TT/4; chunk++) {
                int po = (chunk << 2) | ps4;
                int l  = l0 + po;
                const bool lvalid = (l < LL);     // warp-uniform
                float dpre = gT[dd3*TSTR + po];
                float delta = (dpre > 20.0f) ? dpre : log1pf(__expf(dpre));
                float xcv = xcT[dd3*TSTR + po];
                float dBx = delta * xcv;
                ull dBx2 = pack2(dBx, dBx);
                const float4* bc4 = (const float4*)(dbcBC + po*32);
                ull B2[8], C2[8];
                #pragma unroll
                for (int k = 0; k < 4; k++) {
                    F4U2 v; v.f4 = bc4[k];
                    B2[2*k] = v.u2[0]; B2[2*k+1] = v.u2[1];
                }
                #pragma unroll
                for (int k = 0; k < 4; k++) {
                    F4U2 v; v.f4 = bc4[4+k];
                    C2[2*k] = v.u2[0]; C2[2*k+1] = v.u2[1];
                }
                size_t pos512 = ((size_t)(b*LL + (lvalid ? l : 0))) << 9;
                ull hv2[8];
                if (hmode == 0) {
                    #pragma unroll
                    for (int k = 0; k < 8; k++) hv2[k] = pack2(0.0f, 0.0f);
                } else {
                    #pragma unroll
                    for (int sg = 0; sg < 4; sg++) {
                        F4U2 v;
                        v.f4 = lvalid ? HS[pos512 + (sg<<7) + dd3]
                                      : make_float4(0.f,0.f,0.f,0.f);
                        hv2[2*sg] = v.u2[0]; hv2[2*sg+1] = v.u2[1];
                    }
                }
                ull y2 = pack2(0.0f, 0.0f);
                if (fastA) {
                    float E1 = __expf(-delta);
                    float Esq = E1*E1;
                    ull Echain = pack2(Esq, Esq);
                    ull da = pack2(E1, Esq);
                    #pragma unroll
                    for (int k = 0; k < 8; k++) {
                        ull tmp = mul2(dBx2, B2[k]);
                        ull hn  = fma2(da, hv2[k], tmp);
                        hv2[k] = hn;
                        y2 = fma2(hn, C2[k], y2);
                        if (k < 7) da = mul2(da, Echain);
                    }
                } else {
                    #pragma unroll
                    for (int k = 0; k < 8; k++) {
                        float na0 = __expf(__ldg(&A_log[dd3*16 + 2*k]));
                        float na1 = __expf(__ldg(&A_log[dd3*16 + 2*k + 1]));
                        ull da = pack2(__expf(-delta*na0), __expf(-delta*na1));
                        ull tmp = mul2(dBx2, B2[k]);
                        ull hn  = fma2(da, hv2[k], tmp);
                        hv2[k] = hn;
                        y2 = fma2(hn, C2[k], y2);
                    }
                }
                float ylo, yhi; unpack2(y2, ylo, yhi);
                float y = ylo + yhi;
                if (lvalid) {
                    if (hmode == 2) {
                        #pragma unroll
                        for (int sg = 0; sg < 4; sg++) {
                            F4U2 v; v.u2[0] = hv2[2*sg]; v.u2[1] = hv2[2*sg+1];
                            HD[pos512 + (dd3<<2) + sg] = v.f4;
                        }
                    } else {
                        #pragma unroll
                        for (int sg = 0; sg < 4; sg++) {
                            F4U2 v; v.u2[0] = hv2[2*sg]; v.u2[1] = hv2[2*sg+1];
                            HS[pos512 + (sg<<7) + dd3] = v.f4;
                        }
                    }
                }
                y += Dpv * xcv;
                float zv = z_s[po*128 + dd3];
                gT[dd3*TSTR + po] = y * (zv / (1.0f + __expf(-zv)));
            }
        }
        __syncthreads();

        // ---- phase 3d: out_proj + residual (T4P4, reads gT) ----
        {
            int jt = t & 15;
            int pq = t >> 4;
            if (pq < 14) {
                const int pb = pq*4;
                ull al[4], ah[4];
                #pragma unroll
                for (int i = 0; i < 4; i++) { al[i] = pack2(0,0); ah[i] = pack2(0,0); }
                #pragma unroll 4
                for (int d = 0; d < 128; d++) {
                    F4U2 w; w.f4 = *(const float4*)(outprojT + d*64 + jt*4);
                    float4 g4 = *(const float4*)(gT + d*TSTR + pb);
                    float gs[4] = {g4.x, g4.y, g4.z, g4.w};
                    #pragma unroll
                    for (int i = 0; i < 4; i++) {
                        ull gd = pack2(gs[i], gs[i]);
                        al[i] = fma2(w.u2[0], gd, al[i]);
                        ah[i] = fma2(w.u2[1], gd, ah[i]);
                    }
                }
                #pragma unroll
                for (int i = 0; i < 4; i++) {
                    int l = l0 + pb + i;
                    if (l < LL) {
                        F4U2 o; o.u2[0] = al[i]; o.u2[1] = ah[i];
                        float4 r = ((const float4*)(xn_r + (pb+i)*64))[jt];
                        o.f4.x += r.x; o.f4.y += r.y; o.f4.z += r.z; o.f4.w += r.w;
                        ((float4*)(outp + ((size_t)(b*LL + l))*64))[jt] = o.f4;
                    }
                }
            }
        }

        if (blk < 5) { grid_sync(GRID*ep); ep++; }
    }

    // ================= conv_out stage (pointwise in l: no grid sync) =======
    __syncthreads();
    {
        float* x_s = xn_s;     // [p][65] 3640 <= 3840
        float* wT3 = xcraw_s;  // [c][65]
        float* res = z_s;      // [o][57]
        const float* fin = buf1;   // block 5 wrote buf1
        for (int lin = t; lin < 64*64; lin += NTH)
            wT3[(lin & 63)*65 + (lin >> 6)] = w3[lin];
        for (int lin = t; lin < TT*64; lin += NTH) {
            int p = lin >> 6, c = lin & 63;
            int l = l0 + p;
            x_s[p*65 + c] = (l < LL) ? fin[(size_t)(b*LL + l)*64 + c] : 0.0f;
        }
        __syncthreads();
        int o = t & 63, pslot = t >> 6;
        float bv = b3[o];
        for (int p = pslot; p < TT; p += 8) {
            float acc = bv;
            #pragma unroll 8
            for (int c = 0; c < 64; c++)
                acc += wT3[c*65 + o] * x_s[p*65 + c];
            res[o*57 + p] = acc;
        }
        __syncthreads();
        for (int lin = t; lin < 64*TT; lin += NTH) {
            int oo = lin / TT, p = lin - oo*TT;
            int l = l0 + p;
            if (l < LL) out[(size_t)(b*64 + oo)*LL + l] = res[oo*57 + p];
        }
    }
}

// ---------------- launch ----------------
extern "C" void kernel_launch(void* const* d_in, const int* in_sizes, int n_in,
                              void* d_out, int out_size) {
    const float* rgb   = (const float*)d_in[0];
    const float* dte   = (const float*)d_in[1];
    const float* w1    = (const float*)d_in[2];
    const float* b1    = (const float*)d_in[3];
    const float* w2    = (const float*)d_in[4];
    const float* b2    = (const float*)d_in[5];
    const float* w3    = (const float*)d_in[6];
    const float* b3    = (const float*)d_in[7];
    const float* normw = (const float*)d_in[8];
    const float* inpw  = (const float*)d_in[9];
    const float* c1w   = (const float*)d_in[10];
    const float* c1b   = (const float*)d_in[11];
    const float* xpw   = (const float*)d_in[12];
    const float* dtw   = (const float*)d_in[13];
    const float* dtb   = (const float*)d_in[14];
    const float* alog  = (const float*)d_in[15];
    const float* DpP   = (const float*)d_in[16];
    const float* opw   = (const float*)d_in[17];

    float* out = (float*)d_out;
    const int convN = BB*CC*LL;                  // 524288
    const long long hN = (long long)BB*LL*DI*SS; // 16777216
    float* hfinal;
    if (out_size >= convN + hN) {
        hfinal = out + convN;
    } else {
        void* p; cudaGetSymbolAddress(&p, g_hfallback); hfinal = (float*)p;
    }

    cudaFuncSetAttribute(fused_kernel,
                         cudaFuncAttributeMaxDynamicSharedMemorySize, SMEM_BYTES);

    reset_kernel<<<1, 1>>>();
    fused_kernel<<<GRID, NTH, SMEM_BYTES>>>(
        rgb, dte, w1, b1, w2, b2, w3, b3,
        normw, inpw, c1w, c1b, xpw, dtw, dtb, alog, DpP, opw,
        out, hfinal);
    (void)in_sizes; (void)n_in;
}

// round 13
// speedup vs baseline: 1.0103x; 1.0103x over previous
#include <cuda_runtime.h>
#include <math.h>
#include <stdint.h>

#define BB 2
#define LL 4096
#define CC 64
#define DI 128
#define SS 16
#define TT 56          // positions per tile
#define HT 28          // positions per half-pipeline
#define HR 30          // xcraw rows per half (28 + 2 halo overlap)
#define PST 28         // per-half transposed [d][pos] stride
#define NTILES 74      // ceil(4096/56)
#define NTH 512
#define GRID (BB*NTILES)   // 148 CTAs = one full wave at 1 CTA/SM

typedef unsigned long long ull;
union F4U2 { float4 f4; ull u2[2]; };

__device__ __forceinline__ ull fma2(ull a, ull b, ull c) {
    ull d; asm("fma.rn.f32x2 %0, %1, %2, %3;" : "=l"(d) : "l"(a), "l"(b), "l"(c));
    return d;
}
__device__ __forceinline__ ull mul2(ull a, ull b) {
    ull d; asm("mul.rn.f32x2 %0, %1, %2;" : "=l"(d) : "l"(a), "l"(b));
    return d;
}
__device__ __forceinline__ ull pack2(float lo, float hi) {
    ull d; asm("mov.b64 %0, {%1, %2};" : "=l"(d) : "f"(lo), "f"(hi));
    return d;
}
__device__ __forceinline__ void unpack2(ull v, float& lo, float& hi) {
    asm("mov.b64 {%0, %1}, %2;" : "=f"(lo), "=f"(hi) : "l"(v));
}
// half-pipeline barrier (named, 256 threads)
__device__ __forceinline__ void hbar(int half) {
    asm volatile("bar.sync %0, %1;" :: "r"(half + 1), "r"(256) : "memory");
}

// -------- scratch (device globals; no dynamic allocation allowed) --------
__device__ float g_rgbT[BB*LL*CC];   // [b][l][c]
__device__ float g_dteT[BB*LL*CC];
__device__ float g_buf0[BB*LL*CC];
__device__ float g_buf1[BB*LL*CC];
__device__ float g_wT[64*256];             // in_proj transposed [d][row]
__device__ float g_hperm[BB*LL*DI*SS];     // permuted h chain [b][l][sg][dd][4]
__device__ float g_hfallback[BB*LL*DI*SS]; // final h if out_size unexpected
__device__ unsigned g_bar;                 // grid-sync arrival counter

__global__ void reset_kernel() { g_bar = 0u; }

__device__ __forceinline__ void grid_sync(unsigned target) {
    __syncthreads();
    if (threadIdx.x == 0) {
        __threadfence();
        atomicAdd(&g_bar, 1u);
        while (atomicAdd(&g_bar, 0u) < target) { }
        __threadfence();
    }
    __syncthreads();
}

// smem layout (floats); per-half arrays are [2][halfsize]
#define OFF_XN      0                         // xnT 2 x [64][32] = 4096 (alias conv in_s/x_s)
#define OFF_XNR     (OFF_XN + 4096)           // xn_r 2 x [28][64] = 3584
#define OFF_XCRAW   (OFF_XNR + 3584)          // xcraw 2 x [30][128] = 7680 (alias gT 2x[128][28], conv wT)
#define OFF_Z       (OFF_XCRAW + 7680)        // z 2 x [28][128] = 7168 (alias conv_out res)
#define OFF_XCT     (OFF_Z + 7168)            // xcT 2 x [128][28] = 7168
#define OFF_XPT     (OFF_XCT + 7168)          // 8192
#define OFF_DTT     (OFF_XPT + 8192)          // 4096
#define OFF_OPT     (OFF_DTT + 4096)          // 8192
#define OFF_DBCBC   (OFF_OPT + 8192)          // 2 x [28][32] = 1792
#define OFF_DRAWT   (OFF_DBCBC + 1792)        // 2 x [32][28] = 1792
#define OFF_CW      (OFF_DRAWT + 1792)        // 384
#define OFF_CB      (OFF_CW + 384)            // 128
#define OFF_DTB     (OFF_CB + 128)            // 128
#define OFF_DP      (OFF_DTB + 128)           // 128
#define OFF_NW      (OFF_DP + 128)            // 64
#define SMEM_FLOATS (OFF_NW + 64)
#define SMEM_BYTES  (SMEM_FLOATS * 4)         // ~218 KB

__global__ __launch_bounds__(NTH, 1) void fused_kernel(
    const float* __restrict__ rgb, const float* __restrict__ dte,
    const float* __restrict__ w1, const float* __restrict__ b1,
    const float* __restrict__ w2, const float* __restrict__ b2,
    const float* __restrict__ w3, const float* __restrict__ b3,
    const float* __restrict__ normw,
    const float* __restrict__ in_proj_w,
    const float* __restrict__ conv1d_w, const float* __restrict__ conv1d_b,
    const float* __restrict__ x_proj_w,
    const float* __restrict__ dt_proj_w, const float* __restrict__ dt_proj_b,
    const float* __restrict__ A_log, const float* __restrict__ Dp,
    const float* __restrict__ out_proj_w,
    float* out, float* hfinal)
{
    extern __shared__ float sm[];
    float* xprojT  = sm + OFF_XPT;    // [d][j]
    float* dtprojT = sm + OFF_DTT;    // [r][dd]
    float* outprojT= sm + OFF_OPT;    // [dd][c]
    float* cw_s    = sm + OFF_CW;
    float* cb_s    = sm + OFF_CB;
    float* dtb_s   = sm + OFF_DTB;
    float* Dp_s    = sm + OFF_DP;
    float* nw_s    = sm + OFF_NW;

    const int t    = threadIdx.x;
    const int lane = t & 31;
    const int half = t >> 8;          // 0 or 1
    const int ht   = t & 255;         // thread-in-half
    const int b    = blockIdx.x / NTILES;
    const int tile = blockIdx.x - b*NTILES;
    const int l0   = tile * TT;
    const int hb   = half * HT;       // half's global position base within tile

    // per-half regions
    float* xnT_h   = sm + OFF_XN    + half*2048;   // [c][32], rows hp_local 0..29
    float* xnr_h   = sm + OFF_XNR   + half*1792;   // [p][64]
    float* xcraw_h = sm + OFF_XCRAW + half*3840;   // [r][128], r = hp_local 0..29
    float* z_h     = sm + OFF_Z     + half*3584;   // [p][128]
    float* xcT_h   = sm + OFF_XCT   + half*3584;   // [d][PST]
    float* dbc_h   = sm + OFF_DBCBC + half*896;    // [p][32]: B|C
    float* drawT_h = sm + OFF_DRAWT + half*896;    // [r][PST]
    float* gT_h    = xcraw_h;                      // alias [dd][PST] (delta_pre then g)

    float* rgbT  = g_rgbT;
    float* dteT  = g_dteT;
    float* buf0  = g_buf0;
    float* buf1  = g_buf1;
    float* hperm = g_hperm;

    // fastA: is exp(A_log[dd][s]) == s+1?
    bool fastA = true;
    {
        const int dd3 = t & 127;
        #pragma unroll
        for (int s = 0; s < SS; s++) {
            float na = __expf(A_log[dd3*16 + s]);
            if (fabsf(na - (float)(s+1)) > 1e-3f) fastA = false;
        }
    }

    // ================= conv_in stage (full CTA) =================
    {
        float* in_s = sm + OFF_XN;      // [c][TT] 3584 <= 4096
        float* wT   = sm + OFF_XCRAW;   // [c][65] 4160 <= 7680
        for (int which = 0; which < 2; which++) {
            const float* src  = which ? dte : rgb;
            const float* w    = which ? w2 : w1;
            const float* bias = which ? b2 : b1;
            float* dst = which ? dteT : rgbT;
            __syncthreads();
            for (int lin = t; lin < 64*64; lin += NTH)
                wT[(lin & 63)*65 + (lin >> 6)] = w[lin];
            for (int lin = t; lin < 64*TT; lin += NTH) {
                int c = lin / TT, p = lin - c*TT;
                int l = l0 + p;
                in_s[c*TT + p] = (l < LL) ? src[(size_t)(b*64 + c)*LL + l] : 0.0f;
            }
            __syncthreads();
            int o = t & 63, pslot = t >> 6;
            float bv = bias[o];
            for (int p = pslot; p < TT; p += 8) {
                int l = l0 + p;
                if (l >= LL) continue;
                float acc = bv;
                #pragma unroll 8
                for (int c = 0; c < 64; c++)
                    acc += wT[c*65 + o] * in_s[c*TT + p];
                dst[(size_t)(b*LL + l)*64 + o] = acc;
            }
        }
        __syncthreads();
    }

    // CTA 0 builds the transposed in_proj copy
    if (blockIdx.x == 0) {
        for (int lin = t; lin < 64*256; lin += NTH) {
            int d = lin >> 8, r = lin & 255;
            g_wT[d*256 + r] = in_proj_w[r*64 + d];
        }
    }

    // ================= stage mamba weights (ONCE) =================
    for (int lin = t; lin < 64*128; lin += NTH) {
        int j = lin >> 7, d = lin & 127;
        xprojT[d*64 + j] = x_proj_w[lin];
    }
    for (int lin = t; lin < 128*32; lin += NTH) {
        int dd = lin >> 5, r = lin & 31;
        dtprojT[r*128 + dd] = dt_proj_w[lin];
    }
    for (int lin = t; lin < 64*128; lin += NTH) {
        int c = lin >> 7, dd = lin & 127;
        outprojT[dd*64 + c] = out_proj_w[lin];
    }
    if (t < 384) { int dd = t / 3, k = t % 3; cw_s[k*128 + dd] = conv1d_w[t]; }
    if (t < 128) { cb_s[t] = conv1d_b[t]; dtb_s[t] = dt_proj_b[t]; Dp_s[t] = Dp[t]; }
    if (t < 64)  { nw_s[t] = normw[t]; }

    unsigned ep = 1;
    grid_sync(GRID*ep); ep++;

    // ================= 6 fused residual mamba blocks (two async half-pipes) =====
    for (int blk = 0; blk < 6; blk++) {
        const float* base = (blk & 1) ? dteT : rgbT;
        const float* prev = (blk == 0) ? (const float*)0
                                       : ((blk & 1) ? buf0 : buf1);
        float* outp = (blk & 1) ? buf1 : buf0;
        const int hmode = (blk == 0) ? 0 : (blk == 5 ? 2 : 1);

        // ---- phase 1a: rmsnorm -> xnT_h (rows 0..29) + xnr_h (own 28 pos) ----
        {
            int w = ht >> 5;
            for (int r = w; r < HR; r += 8) {
                int hp = hb + r;                   // global halo-pos 0..57
                int l  = l0 - 1 + hp;              // warp-uniform
                float o0 = 0.0f, o1 = 0.0f;
                if (l >= 0 && l < LL) {
                    size_t off = ((size_t)(b*LL + l)) * 64;
                    float v0 = base[off + lane];
                    float v1 = base[off + 32 + lane];
                    if (prev) { v0 += prev[off + lane]; v1 += prev[off + 32 + lane]; }
                    float ssum = v0*v0 + v1*v1;
                    #pragma unroll
                    for (int m = 16; m > 0; m >>= 1)
                        ssum += __shfl_xor_sync(0xffffffffu, ssum, m);
                    float rs = rsqrtf(ssum * (1.0f/64.0f) + 1e-5f);
                    o0 = v0 * rs * nw_s[lane];
                    o1 = v1 * rs * nw_s[32 + lane];
                }
                xnT_h[lane*32 + r]        = o0;
                xnT_h[(32 + lane)*32 + r] = o1;
                if (r >= 1 && r <= HT) {
                    xnr_h[(r-1)*64 + lane]      = o0;
                    xnr_h[(r-1)*64 + 32 + lane] = o1;
                }
            }
        }
        hbar(half);

        // ---- phase 1b: in_proj GEMM (4 rows x 8 hp / thread; weights LDG) ----
        {
            const int rg = ht & 63;
            const int rb = (ht >> 6) << 3;    // local hp base (0,8,16,24)
            ull accl[8], acch[8];
            #pragma unroll
            for (int i = 0; i < 8; i++) { accl[i] = pack2(0,0); acch[i] = pack2(0,0); }
            const float4* wp = (const float4*)g_wT;
            #pragma unroll 4
            for (int d = 0; d < 64; d++) {
                F4U2 w; w.f4 = __ldg(&wp[d*64 + rg]);
                const float4* xp = (const float4*)(xnT_h + d*32 + rb);
                float4 xa = xp[0], xb = xp[1];
                float xs[8] = {xa.x, xa.y, xa.z, xa.w, xb.x, xb.y, xb.z, xb.w};
                #pragma unroll
                for (int i = 0; i < 8; i++) {
                    ull xd = pack2(xs[i], xs[i]);
                    accl[i] = fma2(w.u2[0], xd, accl[i]);
                    acch[i] = fma2(w.u2[1], xd, acch[i]);
                }
            }
            #pragma unroll
            for (int i = 0; i < 8; i++) {
                int r = rb + i;
                if (r >= HR) break;
                F4U2 v; v.u2[0] = accl[i]; v.u2[1] = acch[i];
                if (rg < 32) {
                    *(float4*)(xcraw_h + r*128 + rg*4) = v.f4;
                } else if (r >= 1 && r <= HT) {
                    *(float4*)(z_h + (r-1)*128 + (rg-32)*4) = v.f4;
                }
            }
        }
        hbar(half);

        // ---- phase 2: dwconv1d + silu -> xcT_h [d][PST] ----
        for (int idx = ht; idx < HT*128; idx += 256) {
            int po = idx >> 7, dd = idx & 127;
            float v = cw_s[dd]         * xcraw_h[po*128 + dd]
                    + cw_s[128 + dd]   * xcraw_h[(po+1)*128 + dd]
                    + cw_s[256 + dd]   * xcraw_h[(po+2)*128 + dd]
                    + cb_s[dd];
            xcT_h[dd*PST + po] = v / (1.0f + __expf(-v));
        }
        hbar(half);

        // ---- phase 3a: x_proj (T4P4) -> dbc_h (B|C) + drawT_h ----
        {
            int jt = ht & 15;
            int pq = ht >> 4;
            if (pq < 7) {
                const int pb = pq*4;
                ull al[4], ah[4];
                #pragma unroll
                for (int i = 0; i < 4; i++) { al[i] = pack2(0,0); ah[i] = pack2(0,0); }
                #pragma unroll 4
                for (int d = 0; d < 128; d++) {
                    F4U2 w; w.f4 = *(const float4*)(xprojT + d*64 + jt*4);
                    float4 x4 = *(const float4*)(xcT_h + d*PST + pb);
                    float xs[4] = {x4.x, x4.y, x4.z, x4.w};
                    #pragma unroll
                    for (int i = 0; i < 4; i++) {
                        ull xd = pack2(xs[i], xs[i]);
                        al[i] = fma2(w.u2[0], xd, al[i]);
                        ah[i] = fma2(w.u2[1], xd, ah[i]);
                    }
                }
                if (jt >= 8) {
                    #pragma unroll
                    for (int i = 0; i < 4; i++) {
                        F4U2 o; o.u2[0] = al[i]; o.u2[1] = ah[i];
                        *(float4*)(dbc_h + (pb+i)*32 + (jt-8)*4) = o.f4;
                    }
                } else {
                    float e0[4], e1[4], e2[4], e3[4];
                    #pragma unroll
                    for (int i = 0; i < 4; i++) {
                        unpack2(al[i], e0[i], e1[i]);
                        unpack2(ah[i], e2[i], e3[i]);
                    }
                    *(float4*)(drawT_h + (jt*4+0)*PST + pb) = make_float4(e0[0],e0[1],e0[2],e0[3]);
                    *(float4*)(drawT_h + (jt*4+1)*PST + pb) = make_float4(e1[0],e1[1],e1[2],e1[3]);
                    *(float4*)(drawT_h + (jt*4+2)*PST + pb) = make_float4(e2[0],e2[1],e2[2],e2[3]);
                    *(float4*)(drawT_h + (jt*4+3)*PST + pb) = make_float4(e3[0],e3[1],e3[2],e3[3]);
                }
            }
        }
        hbar(half);

        // ---- phase 3a2: dt_proj GEMM (K=32) -> delta_pre into gT_h ----
        {
            int dq = ht & 31;
            int pq = ht >> 5;
            if (pq < 7) {
                const int pb = pq*4;
                float b0 = dtb_s[dq*4+0], b1 = dtb_s[dq*4+1];
                float b2v = dtb_s[dq*4+2], b3v = dtb_s[dq*4+3];
                ull al[4], ah[4];
                #pragma unroll
                for (int i = 0; i < 4; i++) { al[i] = pack2(b0,b1); ah[i] = pack2(b2v,b3v); }
                #pragma unroll 4
                for (int r = 0; r < 32; r++) {
                    F4U2 w; w.f4 = *(const float4*)(dtprojT + r*128 + dq*4);
                    float4 x4 = *(const float4*)(drawT_h + r*PST + pb);
                    float xs[4] = {x4.x, x4.y, x4.z, x4.w};
                    #pragma unroll
                    for (int i = 0; i < 4; i++) {
                        ull xd = pack2(xs[i], xs[i]);
                        al[i] = fma2(w.u2[0], xd, al[i]);
                        ah[i] = fma2(w.u2[1], xd, ah[i]);
                    }
                }
                float e0[4], e1[4], e2[4], e3[4];
                #pragma unroll
                for (int i = 0; i < 4; i++) {
                    unpack2(al[i], e0[i], e1[i]);
                    unpack2(ah[i], e2[i], e3[i]);
                }
                *(float4*)(gT_h + (dq*4+0)*PST + pb) = make_float4(e0[0],e0[1],e0[2],e0[3]);
                *(float4*)(gT_h + (dq*4+1)*PST + pb) = make_float4(e1[0],e1[1],e1[2],e1[3]);
                *(float4*)(gT_h + (dq*4+2)*PST + pb) = make_float4(e2[0],e2[1],e2[2],e2[3]);
                *(float4*)(gT_h + (dq*4+3)*PST + pb) = make_float4(e3[0],e3[1],e3[2],e3[3]);
            }
        }
        hbar(half);

        // ---- phase 3bc: softplus, SSM (exp-chain), gating -> gT_h ----
        {
            const int dd3 = ht & 127;
            const int ps  = ht >> 7;   // 0/1 within half
            const float Dpv = Dp_s[dd3];
            float4* HS = (float4*)hperm;
            float4* HD = (float4*)hfinal;
            for (int chunk = 0; chunk < HT/2; chunk++) {
                int po = chunk*2 + ps;             // local 0..27
                int l  = l0 + hb + po;
                const bool lvalid = (l < LL);      // warp-uniform
                float dpre = gT_h[dd3*PST + po];
                float delta = (dpre > 20.0f) ? dpre : log1pf(__expf(dpre));
                float xcv = xcT_h[dd3*PST + po];
                float dBx = delta * xcv;
                ull dBx2 = pack2(dBx, dBx);
                const float4* bc4 = (const float4*)(dbc_h + po*32);
                ull B2[8], C2[8];
                #pragma unroll
                for (int k = 0; k < 4; k++) {
                    F4U2 v; v.f4 = bc4[k];
                    B2[2*k] = v.u2[0]; B2[2*k+1] = v.u2[1];
                }
                #pragma unroll
                for (int k = 0; k < 4; k++) {
                    F4U2 v; v.f4 = bc4[4+k];
                    C2[2*k] = v.u2[0]; C2[2*k+1] = v.u2[1];
                }
                size_t pos512 = ((size_t)(b*LL + (lvalid ? l : 0))) << 9;
                ull hv2[8];
                if (hmode == 0) {
                    #pragma unroll
                    for (int k = 0; k < 8; k++) hv2[k] = pack2(0.0f, 0.0f);
                } else {
                    #pragma unroll
                    for (int sg = 0; sg < 4; sg++) {
                        F4U2 v;
                        v.f4 = lvalid ? HS[pos512 + (sg<<7) + dd3]
                                      : make_float4(0.f,0.f,0.f,0.f);
                        hv2[2*sg] = v.u2[0]; hv2[2*sg+1] = v.u2[1];
                    }
                }
                ull y2 = pack2(0.0f, 0.0f);
                if (fastA) {
                    float E1 = __expf(-delta);
                    float Esq = E1*E1;
                    ull Echain = pack2(Esq, Esq);
                    ull da = pack2(E1, Esq);
                    #pragma unroll
                    for (int k = 0; k < 8; k++) {
                        ull tmp = mul2(dBx2, B2[k]);
                        ull hn  = fma2(da, hv2[k], tmp);
                        hv2[k] = hn;
                        y2 = fma2(hn, C2[k], y2);
                        if (k < 7) da = mul2(da, Echain);
                    }
                } else {
                    #pragma unroll
                    for (int k = 0; k < 8; k++) {
                        float na0 = __expf(__ldg(&A_log[dd3*16 + 2*k]));
                        float na1 = __expf(__ldg(&A_log[dd3*16 + 2*k + 1]));
                        ull da = pack2(__expf(-delta*na0), __expf(-delta*na1));
                        ull tmp = mul2(dBx2, B2[k]);
                        ull hn  = fma2(da, hv2[k], tmp);
                        hv2[k] = hn;
                        y2 = fma2(hn, C2[k], y2);
                    }
                }
                float ylo, yhi; unpack2(y2, ylo, yhi);
                float y = ylo + yhi;
                if (lvalid) {
                    if (hmode == 2) {
                        #pragma unroll
                        for (int sg = 0; sg < 4; sg++) {
                            F4U2 v; v.u2[0] = hv2[2*sg]; v.u2[1] = hv2[2*sg+1];
                            HD[pos512 + (dd3<<2) + sg] = v.f4;
                        }
                    } else {
                        #pragma unroll
                        for (int sg = 0; sg < 4; sg++) {
                            F4U2 v; v.u2[0] = hv2[2*sg]; v.u2[1] = hv2[2*sg+1];
                            HS[pos512 + (sg<<7) + dd3] = v.f4;
                        }
                    }
                }
                y += Dpv * xcv;
                float zv = z_h[po*128 + dd3];
                gT_h[dd3*PST + po] = y * (zv / (1.0f + __expf(-zv)));
            }
        }
        hbar(half);

        // ---- phase 3d: out_proj + residual (T4P4, reads gT_h) ----
        {
            int jt = ht & 15;
            int pq = ht >> 4;
            if (pq < 7) {
                const int pb = pq*4;
                ull al[4], ah[4];
                #pragma unroll
                for (int i = 0; i < 4; i++) { al[i] = pack2(0,0); ah[i] = pack2(0,0); }
                #pragma unroll 4
                for (int d = 0; d < 128; d++) {
                    F4U2 w; w.f4 = *(const float4*)(outprojT + d*64 + jt*4);
                    float4 g4 = *(const float4*)(gT_h + d*PST + pb);
                    float gs[4] = {g4.x, g4.y, g4.z, g4.w};
                    #pragma unroll
                    for (int i = 0; i < 4; i++) {
                        ull gd = pack2(gs[i], gs[i]);
                        al[i] = fma2(w.u2[0], gd, al[i]);
                        ah[i] = fma2(w.u2[1], gd, ah[i]);
                    }
                }
                #pragma unroll
                for (int i = 0; i < 4; i++) {
                    int l = l0 + hb + pb + i;
                    if (l < LL) {
                        F4U2 o; o.u2[0] = al[i]; o.u2[1] = ah[i];
                        float4 r = ((const float4*)(xnr_h + (pb+i)*64))[jt];
                        o.f4.x += r.x; o.f4.y += r.y; o.f4.z += r.z; o.f4.w += r.w;
                        ((float4*)(outp + ((size_t)(b*LL + l))*64))[jt] = o.f4;
                    }
                }
            }
        }

        if (blk < 5) { grid_sync(GRID*ep); ep++; }   // joins both halves
    }

    // ================= conv_out stage (full CTA; pointwise in l) =======
    __syncthreads();   // joins both halves after block 5
    {
        float* x_s = sm + OFF_XN;      // [p][65] 3640 <= 4096
        float* wT3 = sm + OFF_XCRAW;   // [c][65]
        float* res = sm + OFF_Z;       // [o][57] 3648 <= 7168
        const float* fin = buf1;       // block 5 wrote buf1
        for (int lin = t; lin < 64*64; lin += NTH)
            wT3[(lin & 63)*65 + (lin >> 6)] = w3[lin];
        for (int lin = t; lin < TT*64; lin += NTH) {
            int p = lin >> 6, c = lin & 63;
            int l = l0 + p;
            x_s[p*65 + c] = (l < LL) ? fin[(size_t)(b*LL + l)*64 + c] : 0.0f;
        }
        __syncthreads();
        int o = t & 63, pslot = t >> 6;
        float bv = b3[o];
        for (int p = pslot; p < TT; p += 8) {
            float acc = bv;
            #pragma unroll 8
            for (int c = 0; c < 64; c++)
                acc += wT3[c*65 + o] * x_s[p*65 + c];
            res[o*57 + p] = acc;
        }
        __syncthreads();
        for (int lin = t; lin < 64*TT; lin += NTH) {
            int oo = lin / TT, p = lin - oo*TT;
            int l = l0 + p;
            if (l < LL) out[(size_t)(b*64 + oo)*LL + l] = res[oo*57 + p];
        }
    }
}

// ---------------- launch ----------------
extern "C" void kernel_launch(void* const* d_in, const int* in_sizes, int n_in,
                              void* d_out, int out_size) {
    const float* rgb   = (const float*)d_in[0];
    const float* dte   = (const float*)d_in[1];
    const float* w1    = (const float*)d_in[2];
    const float* b1    = (const float*)d_in[3];
    const float* w2    = (const float*)d_in[4];
    const float* b2    = (const float*)d_in[5];
    const float* w3    = (const float*)d_in[6];
    const float* b3    = (const float*)d_in[7];
    const float* normw = (const float*)d_in[8];
    const float* inpw  = (const float*)d_in[9];
    const float* c1w   = (const float*)d_in[10];
    const float* c1b   = (const float*)d_in[11];
    const float* xpw   = (const float*)d_in[12];
    const float* dtw   = (const float*)d_in[13];
    const float* dtb   = (const float*)d_in[14];
    const float* alog  = (const float*)d_in[15];
    const float* DpP   = (const float*)d_in[16];
    const float* opw   = (const float*)d_in[17];

    float* out = (float*)d_out;
    const int convN = BB*CC*LL;                  // 524288
    const long long hN = (long long)BB*LL*DI*SS; // 16777216
    float* hfinal;
    if (out_size >= convN + hN) {
        hfinal = out + convN;
    } else {
        void* p; cudaGetSymbolAddress(&p, g_hfallback); hfinal = (float*)p;
    }

    cudaFuncSetAttribute(fused_kernel,
                         cudaFuncAttributeMaxDynamicSharedMemorySize, SMEM_BYTES);

    reset_kernel<<<1, 1>>>();
    fused_kernel<<<GRID, NTH, SMEM_BYTES>>>(
        rgb, dte, w1, b1, w2, b2, w3, b3,
        normw, inpw, c1w, c1b, xpw, dtw, dtb, alog, DpP, opw,
        out, hfinal);
    (void)in_sizes; (void)n_in;
}